// round 9
// baseline (speedup 1.0000x reference)
#include <cuda_runtime.h>
#include <cuda_fp16.h>
#include <math.h>

#define NN 100000
#define EE 3200000
#define NB 98   // ceil(NN/1024)

typedef unsigned long long u64;

__device__ __forceinline__ u64 pk(float a, float b) {
    u64 r; asm("mov.b64 %0,{%1,%2};" : "=l"(r) : "f"(a), "f"(b)); return r;
}
__device__ __forceinline__ void upk(u64 v, float& a, float& b) {
    asm("mov.b64 {%0,%1},%2;" : "=f"(a), "=f"(b) : "l"(v));
}
__device__ __forceinline__ void ffma2(u64& d, u64 a, u64 b) {
    asm("fma.rn.f32x2 %0,%1,%2,%0;" : "+l"(d) : "l"(a), "l"(b));
}

// ---------------- device scratch ----------------
__device__ __align__(16) u64    g_Hp[16 * NN];      // H paired: [k][n] = (H[2k],H[2k+1])
__device__ __align__(16) u64    g_vt1[16 * NN];     // lp-ReLU paired
__device__ __align__(16) __half g_PdtH[NN * 32];
__device__ __align__(16) __half g_PdfH[NN * 32];
__device__ __align__(16) __half g_PstH[NN * 32];
__device__ __align__(16) __half g_PsfH[NN * 32];
__device__ __align__(16) float g_sum_to[NN * 32];
__device__ __align__(16) float g_sum_fr[NN * 32];
__device__ int   g_cnt_to[NN];
__device__ int   g_cnt_fr[NN];
__device__ float g_selfsum[NN];
__device__ float g_loss[4];

// CSR
__device__ int g_rowp_to[NN + 1];
__device__ int g_rowp_fr[NN + 1];
__device__ int g_cur_to[NN];
__device__ int g_cur_fr[NN];
__device__ __align__(16) u64 g_pay_to[EE];
__device__ __align__(16) u64 g_pay_fr[EE];
__device__ int g_blks[2 * NB];

// packed/folded weights
__device__ __align__(16) float g_G[96 * 132];
__device__ __align__(16) u64   g_Gp[132 * 48];      // [j][qp] = (G[2qp][j], G[2qp+1][j])
__device__ float g_bias[96];
__device__ float g_cto[96];
__device__ float g_cfr[96];
__device__ __align__(16) float g_ew[192];

// ---------------- init ----------------
__global__ void k_init() {
    int t = blockIdx.x * blockDim.x + threadIdx.x;
    int nt = gridDim.x * blockDim.x;
    __half hz = __float2half(0.f);
    for (int i = t; i < 16 * NN; i += nt) g_Hp[i] = 0ull;
    for (int i = t; i < 32 * NN; i += nt) {
        g_PdtH[i] = hz; g_PdfH[i] = hz; g_PstH[i] = hz; g_PsfH[i] = hz;
    }
    for (int i = t; i < NN; i += nt) {
        g_cnt_to[i] = 0; g_cnt_fr[i] = 0; g_selfsum[i] = 0.f;
    }
    if (t < 4) g_loss[t] = 0.f;
}

__global__ void k_count(const int* __restrict__ ei, const float* __restrict__ ea) {
    int e = blockIdx.x * blockDim.x + threadIdx.x;
    if (e >= EE) return;
    int s = ei[e];
    int d = ei[EE + e];
    if (s != d) {
        atomicAdd(&g_cnt_to[d], 1);
        atomicAdd(&g_cnt_fr[s], 1);
    } else {
        atomicAdd(&g_selfsum[s], ea[2 * e]);
    }
}

// ---------------- CSR build ----------------
__global__ void k_scanA() {
    __shared__ int sh[1024];
    int arr = blockIdx.y;
    int i = blockIdx.x * 1024 + threadIdx.x;
    const int* cnt = arr ? g_cnt_fr : g_cnt_to;
    int* rowp = arr ? g_rowp_fr : g_rowp_to;
    int v = (i < NN) ? cnt[i] : 0;
    sh[threadIdx.x] = v;
    __syncthreads();
#pragma unroll
    for (int off = 1; off < 1024; off <<= 1) {
        int t2 = (threadIdx.x >= off) ? sh[threadIdx.x - off] : 0;
        __syncthreads();
        sh[threadIdx.x] += t2;
        __syncthreads();
    }
    if (i < NN) rowp[i] = sh[threadIdx.x] - v;
    if (threadIdx.x == 1023) g_blks[arr * NB + blockIdx.x] = sh[1023];
}

__global__ void k_scanB() {
    int t = threadIdx.x;
    if (t < 2) {
        int acc = 0;
        for (int b = 0; b < NB; b++) {
            int v = g_blks[t * NB + b];
            g_blks[t * NB + b] = acc;
            acc += v;
        }
        (t ? g_rowp_fr : g_rowp_to)[NN] = acc;
    }
}

__global__ void k_scanC() {
    int arr = blockIdx.y;
    int i = blockIdx.x * 1024 + threadIdx.x;
    if (i >= NN) return;
    int* rowp = arr ? g_rowp_fr : g_rowp_to;
    int* cur  = arr ? g_cur_fr  : g_cur_to;
    int v = rowp[i] + g_blks[arr * NB + blockIdx.x];
    rowp[i] = v;
    cur[i] = v;
}

__global__ void k_scatter(const int* __restrict__ ei, const float* __restrict__ ea) {
    int e = blockIdx.x * blockDim.x + threadIdx.x;
    if (e >= EE) return;
    int s = ei[e];
    int d = ei[EE + e];
    if (s == d) return;
    __half2 eh = __floats2half2_rn(ea[2 * e], ea[2 * e + 1]);
    unsigned ehu = *(unsigned*)&eh;
    u64 hi = ((u64)ehu) << 32;
    int p1 = atomicAdd(&g_cur_to[d], 1);
    g_pay_to[p1] = hi | (unsigned)s;
    int p2 = atomicAdd(&g_cur_fr[s], 1);
    g_pay_fr[p2] = hi | (unsigned)d;
}

// ---------------- weight folding ----------------
__global__ void k_pack(const float* __restrict__ Wih, const float* __restrict__ bih,
                       const float* __restrict__ bhh,
                       const float* __restrict__ toW2, const float* __restrict__ tob2,
                       const float* __restrict__ frW2, const float* __restrict__ frb2,
                       const float* __restrict__ lpW2, const float* __restrict__ lpb2,
                       const float* __restrict__ toW1, const float* __restrict__ tob1,
                       const float* __restrict__ frW1, const float* __restrict__ frb1) {
    int t = blockIdx.x * blockDim.x + threadIdx.x;
    int nt = gridDim.x * blockDim.x;
    for (int idx = t; idx < 96 * 132; idx += nt) {
        int q = idx / 132, c = idx - q * 132;
        float v = 0.f;
        if (c < 32) {
            v = Wih[q * 131 + c];
        } else if (c < 64) {
            int j = c - 32;
            for (int i = 0; i < 32; i++) v += Wih[q * 131 + 32 + i] * toW2[i * 32 + j];
        } else if (c < 96) {
            int j = c - 64;
            for (int i = 0; i < 32; i++) v += Wih[q * 131 + 64 + i] * frW2[i * 32 + j];
        } else if (c < 128) {
            int j = c - 96;
            for (int i = 0; i < 32; i++) v += Wih[q * 131 + 96 + i] * lpW2[i * 32 + j];
        } else if (c < 131) {
            v = Wih[q * 131 + 128 + (c - 128)];
        }
        g_G[idx] = v;
    }
    for (int q = t; q < 96; q += nt) {
        float b = bih[q], ct = 0.f, cf = 0.f;
        for (int i = 0; i < 32; i++) {
            b  += Wih[q * 131 + 96 + i] * lpb2[i];
            ct += Wih[q * 131 + 32 + i] * tob2[i];
            cf += Wih[q * 131 + 64 + i] * frb2[i];
        }
        if (q < 64) b += bhh[q];
        g_bias[q] = b; g_cto[q] = ct; g_cfr[q] = cf;
    }
    for (int i = t; i < 192; i += nt) {
        int r = i >> 5, j = i & 31;
        float v;
        if      (r == 0) v = toW1[j * 66 + 64];
        else if (r == 1) v = toW1[j * 66 + 65];
        else if (r == 2) v = tob1[j];
        else if (r == 3) v = frW1[j * 66 + 64];
        else if (r == 4) v = frW1[j * 66 + 65];
        else             v = frb1[j];
        g_ew[i] = v;
    }
}

__global__ void k_pack2() {
    int t = blockIdx.x * blockDim.x + threadIdx.x;
    int nt = gridDim.x * blockDim.x;
    for (int idx = t; idx < 132 * 48; idx += nt) {
        int j = idx / 48, qp = idx - j * 48;
        g_Gp[idx] = pk(g_G[(2 * qp) * 132 + j], g_G[(2 * qp + 1) * 132 + j]);
    }
}

// ---------------- k_lp0: vt1 for H = 0 ----------------
__global__ void k_lp0(const float* __restrict__ lpW1, const float* __restrict__ lpb1) {
    int n = blockIdx.x * blockDim.x + threadIdx.x;
    if (n >= NN) return;
    float lc = -g_selfsum[n];
#pragma unroll
    for (int k = 0; k < 16; k++) {
        float v0 = fmaxf(__ldg(&lpb1[2 * k])     + __ldg(&lpW1[(2 * k) * 65 + 64]) * lc, 0.f);
        float v1 = fmaxf(__ldg(&lpb1[2 * k + 1]) + __ldg(&lpW1[(2 * k + 1) * 65 + 64]) * lc, 0.f);
        g_vt1[k * NN + n] = pk(v0, v1);
    }
}

// ---------------- edge pass: warp-per-node gather-reduce ----------------
__global__ __launch_bounds__(256) void k_pass() {
    int gwarp = (blockIdx.x * 256 + threadIdx.x) >> 5;
    int lane = threadIdx.x & 31;
    int dir = gwarp >= NN;
    int n = gwarp - dir * NN;
    if (n >= NN) return;

    const int*    rowp = dir ? g_rowp_fr : g_rowp_to;
    const u64*    pay  = dir ? g_pay_fr  : g_pay_to;
    const __half* stat = dir ? g_PsfH    : g_PdtH;
    const __half* gat  = dir ? g_PdfH    : g_PstH;
    float*        outp = dir ? g_sum_fr  : g_sum_to;

    float wa0 = __ldg(&g_ew[dir * 96 + lane]);
    float wa1 = __ldg(&g_ew[dir * 96 + 32 + lane]);
    float bb  = __ldg(&g_ew[dir * 96 + 64 + lane]);

    int beg = __ldg(&rowp[n]);
    int end = __ldg(&rowp[n + 1]);
    float st = __half2float(stat[n * 32 + lane]);
    float base = st + bb;
    float acc = 0.f;

    int e = beg;
    if ((e & 1) && e < end) {           // peel to 16B alignment
        u64 p = __ldg(&pay[e]);
        int idx = (int)(unsigned)p;
        unsigned ehu = (unsigned)(p >> 32);
        float2 eaf = __half22float2(*(__half2*)&ehu);
        float g = __half2float(__ldg(&gat[idx * 32 + lane]));
        acc += fmaxf(base + g + eaf.x * wa0 + eaf.y * wa1, 0.f);
        e++;
    }
    for (; e + 1 < end; e += 2) {       // 2 payloads per LDG.128
        uint4 p2 = __ldg((const uint4*)&pay[e]);
        float2 ea0 = __half22float2(*(__half2*)&p2.y);
        float2 ea1 = __half22float2(*(__half2*)&p2.w);
        float g0 = __half2float(__ldg(&gat[(int)p2.x * 32 + lane]));
        float g1 = __half2float(__ldg(&gat[(int)p2.z * 32 + lane]));
        acc += fmaxf(base + g0 + ea0.x * wa0 + ea0.y * wa1, 0.f);
        acc += fmaxf(base + g1 + ea1.x * wa0 + ea1.y * wa1, 0.f);
    }
    if (e < end) {
        u64 p = __ldg(&pay[e]);
        int idx = (int)(unsigned)p;
        unsigned ehu = (unsigned)(p >> 32);
        float2 eaf = __half22float2(*(__half2*)&ehu);
        float g = __half2float(__ldg(&gat[idx * 32 + lane]));
        acc += fmaxf(base + g + eaf.x * wa0 + eaf.y * wa1, 0.f);
    }
    outp[n * 32 + lane] = acc;
}

// ---------------- k_gru: output-stationary GEMV, inputs streamed from source ----------------
__device__ __forceinline__ void consume(u64* acc, const u64* sGp, int j2, u64 c) {
    float v0, v1; upk(c, v0, v1);
    u64 s0 = pk(v0, v0), s1 = pk(v1, v1);
    const u64* w0p = &sGp[(2 * j2) * 48];
    const u64* w1p = w0p + 48;
#pragma unroll
    for (int qb = 0; qb < 24; qb++) {
        ulonglong2 w = *(const ulonglong2*)&w0p[qb * 2];
        ffma2(acc[qb * 2], w.x, s0);
        ffma2(acc[qb * 2 + 1], w.y, s0);
    }
#pragma unroll
    for (int qb = 0; qb < 24; qb++) {
        ulonglong2 w = *(const ulonglong2*)&w1p[qb * 2];
        ffma2(acc[qb * 2], w.x, s1);
        ffma2(acc[qb * 2 + 1], w.y, s1);
    }
}

__global__ __launch_bounds__(128, 3) void k_gru(const float* __restrict__ bhh,
                                                const float* __restrict__ x) {
    extern __shared__ u64 smu[];
    u64*   sGp  = smu;                       // 6336 u64
    float* sb   = (float*)(smu + 6336);      // 96
    float* sct  = sb + 96;                   // 96
    float* scf  = sct + 96;                  // 96
    float* sbhn = scf + 96;                  // 32

    for (int i = threadIdx.x; i < 6336; i += 128) sGp[i] = g_Gp[i];
    for (int i = threadIdx.x; i < 96; i += 128) {
        sb[i] = g_bias[i]; sct[i] = g_cto[i]; scf[i] = g_cfr[i];
    }
    if (threadIdx.x < 32) sbhn[threadIdx.x] = bhh[64 + threadIdx.x];
    __syncthreads();

    int n = blockIdx.x * 128 + threadIdx.x;
    if (n >= NN) return;

    int ct = __ldg(&g_cnt_to[n]), cf = __ldg(&g_cnt_fr[n]);
    float rt = ct > 0 ? 1.f / (float)ct : 0.f;
    float rf = cf > 0 ? 1.f / (float)cf : 0.f;
    float ft = ct > 0 ? 1.f : 0.f;
    float ff = cf > 0 ? 1.f : 0.f;

    u64 acc[48];
#pragma unroll
    for (int qp = 0; qp < 48; qp++) {
        int q0 = 2 * qp, q1 = q0 + 1;
        acc[qp] = pk(sb[q0] + ft * sct[q0] + ff * scf[q0],
                     sb[q1] + ft * sct[q1] + ff * scf[q1]);
    }

    // H block (j2 = 0..15), prefetch 1 ahead
    {
        u64 c = __ldg(&g_Hp[n]);
        for (int k = 0; k < 16; k++) {
            u64 nc = (k < 15) ? __ldg(&g_Hp[(k + 1) * NN + n]) : 0ull;
            consume(acc, sGp, k, c);
            c = nc;
        }
    }
    // m_to block (j2 = 16..31)
    {
        float4 a = __ldg((const float4*)&g_sum_to[n * 32]);
        for (int j4 = 0; j4 < 8; j4++) {
            float4 na = (j4 < 7) ? __ldg((const float4*)&g_sum_to[n * 32 + (j4 + 1) * 4])
                                 : make_float4(0.f, 0.f, 0.f, 0.f);
            consume(acc, sGp, 16 + 2 * j4, pk(a.x * rt, a.y * rt));
            consume(acc, sGp, 17 + 2 * j4, pk(a.z * rt, a.w * rt));
            a = na;
        }
    }
    // m_fr block (j2 = 32..47)
    {
        float4 a = __ldg((const float4*)&g_sum_fr[n * 32]);
        for (int j4 = 0; j4 < 8; j4++) {
            float4 na = (j4 < 7) ? __ldg((const float4*)&g_sum_fr[n * 32 + (j4 + 1) * 4])
                                 : make_float4(0.f, 0.f, 0.f, 0.f);
            consume(acc, sGp, 32 + 2 * j4, pk(a.x * rf, a.y * rf));
            consume(acc, sGp, 33 + 2 * j4, pk(a.z * rf, a.w * rf));
            a = na;
        }
    }
    // vt1 block (j2 = 48..63)
    {
        u64 c = __ldg(&g_vt1[n]);
        for (int k = 0; k < 16; k++) {
            u64 nc = (k < 15) ? __ldg(&g_vt1[(k + 1) * NN + n]) : 0ull;
            consume(acc, sGp, 48 + k, c);
            c = nc;
        }
    }
    // x block (j2 = 64..65)
    {
        float x0 = __ldg(&x[n * 3]), x1 = __ldg(&x[n * 3 + 1]), x2 = __ldg(&x[n * 3 + 2]);
        consume(acc, sGp, 64, pk(x0, x1));
        consume(acc, sGp, 65, pk(x2, 0.f));
    }

#pragma unroll
    for (int i = 0; i < 16; i++) {
        float aR0, aR1, aZ0, aZ1, aN0, aN1;
        upk(acc[i], aR0, aR1);
        upk(acc[16 + i], aZ0, aZ1);
        upk(acc[32 + i], aN0, aN1);
        int q0 = 2 * i, q1 = q0 + 1;
        float r0 = 1.f / (1.f + __expf(-aR0));
        float r1 = 1.f / (1.f + __expf(-aR1));
        float z0 = 1.f / (1.f + __expf(-aZ0));
        float z1 = 1.f / (1.f + __expf(-aZ1));
        float tn0 = aN0 + r0 * sbhn[q0];
        float tn1 = aN1 + r1 * sbhn[q1];
        float th0 = 2.f / (1.f + __expf(-2.f * tn0)) - 1.f;
        float th1 = 2.f / (1.f + __expf(-2.f * tn1)) - 1.f;
        float h0, h1; upk(g_Hp[i * NN + n], h0, h1);
        h0 += 0.5f * (1.f - z0) * th0;   // ALPHA = 0.5
        h1 += 0.5f * (1.f - z1) * th1;
        g_Hp[i * NN + n] = pk(h0, h1);
    }
}

// ---------------- k_post: proj (y-split) + decode/loss + lp for next step ----------------
__global__ __launch_bounds__(128) void k_post(
        const float* __restrict__ toW1, const float* __restrict__ frW1,
        const float* __restrict__ lpW1, const float* __restrict__ lpb1,
        const float* __restrict__ dec1, const float* __restrict__ decb1,
        const float* __restrict__ dec2, const float* __restrict__ decb2,
        const float* __restrict__ y, float* __restrict__ outF,
        int do_proj, int loss_idx) {
    __shared__ float sPA[2048];
    __shared__ float sD1[1024];
    __shared__ float sD2[64];
    __shared__ float sDb1[32];
    __shared__ float sDb2[2];
    __shared__ float sW1f[1152];   // stride 36
    __shared__ float sb1[32];

    int half = blockIdx.y;
    if (do_proj) {
        for (int i = threadIdx.x; i < 2048; i += 128) {
            int m = half * 2 + (i >> 10), r = i & 1023, ii = r >> 5, j = r & 31;
            float v;
            if (m == 0)      v = toW1[ii * 66 + j];        // Pdt
            else if (m == 1) v = frW1[ii * 66 + 32 + j];   // Pdf
            else if (m == 2) v = toW1[ii * 66 + 32 + j];   // Pst
            else             v = frW1[ii * 66 + j];        // Psf
            sPA[i] = v;
        }
    }
    if (half == 0) {
        for (int i = threadIdx.x; i < 1024; i += 128) sD1[i] = dec1[i];
        if (threadIdx.x < 64) sD2[threadIdx.x] = dec2[threadIdx.x];
        if (threadIdx.x < 32) sDb1[threadIdx.x] = decb1[threadIdx.x];
        if (threadIdx.x < 2)  sDb2[threadIdx.x] = decb2[threadIdx.x];
    } else if (do_proj) {
        for (int i = threadIdx.x; i < 1152; i += 128) {
            int tq = i / 36, c = i - tq * 36;
            float v = 0.f;
            if (c < 32)       v = lpW1[tq * 65 + c] + lpW1[tq * 65 + 32 + c];
            else if (c == 32) v = lpW1[tq * 65 + 64];
            sW1f[i] = v;
        }
        if (threadIdx.x < 32) sb1[threadIdx.x] = lpb1[threadIdx.x];
    }
    __syncthreads();

    int n = blockIdx.x * 128 + threadIdx.x;
    if (n >= NN) return;

    u64 vHp[16];
#pragma unroll
    for (int k = 0; k < 16; k++) vHp[k] = __ldg(&g_Hp[k * NN + n]);

    if (do_proj) {
        __half* outA = half ? g_PstH : g_PdtH;
        __half* outB = half ? g_PsfH : g_PdfH;
        for (int i4 = 0; i4 < 8; i4++) {
            u64 A[8];
#pragma unroll
            for (int t = 0; t < 8; t++) A[t] = 0ull;
#pragma unroll
            for (int j4 = 0; j4 < 8; j4++) {
                u64 vlo = vHp[j4 * 2], vhi = vHp[j4 * 2 + 1];
#pragma unroll
                for (int mm = 0; mm < 2; mm++) {
#pragma unroll
                    for (int ii = 0; ii < 4; ii++) {
                        ulonglong2 w = *(const ulonglong2*)&sPA[mm * 1024 + (i4 * 4 + ii) * 32 + j4 * 4];
                        ffma2(A[mm * 4 + ii], w.x, vlo);
                        ffma2(A[mm * 4 + ii], w.y, vhi);
                    }
                }
            }
            __half2 hA01, hA23, hB01, hB23;
            float l0, h0, l1, h1, l2, h2, l3, h3;
            upk(A[0], l0, h0); upk(A[1], l1, h1); upk(A[2], l2, h2); upk(A[3], l3, h3);
            hA01 = __floats2half2_rn(l0 + h0, l1 + h1);
            hA23 = __floats2half2_rn(l2 + h2, l3 + h3);
            upk(A[4], l0, h0); upk(A[5], l1, h1); upk(A[6], l2, h2); upk(A[7], l3, h3);
            hB01 = __floats2half2_rn(l0 + h0, l1 + h1);
            hB23 = __floats2half2_rn(l2 + h2, l3 + h3);
            uint2 stA, stB;
            stA.x = *(unsigned*)&hA01; stA.y = *(unsigned*)&hA23;
            stB.x = *(unsigned*)&hB01; stB.y = *(unsigned*)&hB23;
            *(uint2*)&outA[n * 32 + i4 * 4] = stA;
            *(uint2*)&outB[n * 32 + i4 * 4] = stB;
        }
    }

    if (half == 0) {
        float F0 = sDb2[0], F1 = sDb2[1];
        for (int i = 0; i < 32; i++) {
            u64 acc = pk(sDb1[i], 0.f);
#pragma unroll
            for (int j4 = 0; j4 < 8; j4++) {
                ulonglong2 w = *(const ulonglong2*)&sD1[i * 32 + j4 * 4];
                ffma2(acc, w.x, vHp[j4 * 2]);
                ffma2(acc, w.y, vHp[j4 * 2 + 1]);
            }
            float lo, hi; upk(acc, lo, hi);
            float a = fmaxf(lo + hi, 0.f);
            F0 += sD2[i] * a;
            F1 += sD2[32 + i] * a;
        }
        float d0 = F0 - y[n * 2], d1 = F1 - y[n * 2 + 1];
        float sse = d0 * d0 + d1 * d1;
        if (outF) { outF[n * 2] = F0; outF[n * 2 + 1] = F1; }
#pragma unroll
        for (int o = 16; o; o >>= 1) sse += __shfl_down_sync(0xffffffffu, sse, o);
        if ((threadIdx.x & 31) == 0) atomicAdd(&g_loss[loss_idx], sse);
    } else if (do_proj) {
        // lp(H_new) -> vt1 for next step's GRU
        float lc = -g_selfsum[n];
#pragma unroll
        for (int i2 = 0; i2 < 16; i2++) {
            int i0 = 2 * i2;
            u64 acc0 = pk(sb1[i0]     + sW1f[i0 * 36 + 32] * lc, 0.f);
            u64 acc1 = pk(sb1[i0 + 1] + sW1f[(i0 + 1) * 36 + 32] * lc, 0.f);
#pragma unroll
            for (int j4 = 0; j4 < 8; j4++) {
                ulonglong2 w0 = *(const ulonglong2*)&sW1f[i0 * 36 + j4 * 4];
                ulonglong2 w1 = *(const ulonglong2*)&sW1f[(i0 + 1) * 36 + j4 * 4];
                ffma2(acc0, w0.x, vHp[j4 * 2]); ffma2(acc0, w0.y, vHp[j4 * 2 + 1]);
                ffma2(acc1, w1.x, vHp[j4 * 2]); ffma2(acc1, w1.y, vHp[j4 * 2 + 1]);
            }
            float a0, b0, a1, b1;
            upk(acc0, a0, b0); upk(acc1, a1, b1);
            g_vt1[i2 * NN + n] = pk(fmaxf(a0 + b0, 0.f), fmaxf(a1 + b1, 0.f));
        }
    }
}

// ---------------- finalize losses ----------------
__global__ void k_final(float* __restrict__ out) {
    if (blockIdx.x == 0 && threadIdx.x == 0) {
        float inv = 1.f / (2.f * (float)NN);
        float l0 = g_loss[0] * inv;
        float l1 = g_loss[1] * inv;
        float l2 = g_loss[2] * inv;
        float l3 = g_loss[3] * inv;
        out[200000] = 0.729f * l0 + 0.81f * l1 + 0.9f * l2 + l3;
        out[200001] = l0; out[200002] = l1; out[200003] = l2; out[200004] = l3;
    }
}

// ---------------- launch ----------------
extern "C" void kernel_launch(void* const* d_in, const int* in_sizes, int n_in,
                              void* d_out, int out_size) {
    const float* x    = (const float*)d_in[0];
    const float* y    = (const float*)d_in[1];
    const int*   ei   = (const int*)d_in[2];
    const float* ea   = (const float*)d_in[3];
    const float* toW1 = (const float*)d_in[4];
    const float* tob1 = (const float*)d_in[5];
    const float* toW2 = (const float*)d_in[6];
    const float* tob2 = (const float*)d_in[7];
    const float* frW1 = (const float*)d_in[8];
    const float* frb1 = (const float*)d_in[9];
    const float* frW2 = (const float*)d_in[10];
    const float* frb2 = (const float*)d_in[11];
    const float* lpW1 = (const float*)d_in[12];
    const float* lpb1 = (const float*)d_in[13];
    const float* lpW2 = (const float*)d_in[14];
    const float* lpb2 = (const float*)d_in[15];
    const float* Wih  = (const float*)d_in[16];
    const float* bih  = (const float*)d_in[17];
    // d_in[18] = gru_Whh (unused: h0 = 0)
    const float* bhh  = (const float*)d_in[19];
    const float* dec1 = (const float*)d_in[20];
    const float* decb1= (const float*)d_in[21];
    const float* dec2 = (const float*)d_in[22];
    const float* decb2= (const float*)d_in[23];
    float* out = (float*)d_out;

    const int gru_smem = 6336 * 8 + 320 * 4;   // 51968 bytes
    cudaFuncSetAttribute(k_gru, cudaFuncAttributeMaxDynamicSharedMemorySize, gru_smem);

    k_init<<<1024, 256>>>();
    k_count<<<(EE + 255) / 256, 256>>>(ei, ea);
    k_pack<<<8, 256>>>(Wih, bih, bhh, toW2, tob2, frW2, frb2, lpW2, lpb2,
                       toW1, tob1, frW1, frb1);
    k_pack2<<<8, 256>>>();
    dim3 sgrid(NB, 2);
    k_scanA<<<sgrid, 1024>>>();
    k_scanB<<<1, 32>>>();
    k_scanC<<<sgrid, 1024>>>();
    k_scatter<<<(EE + 255) / 256, 256>>>(ei, ea);
    k_lp0<<<(NN + 255) / 256, 256>>>(lpW1, lpb1);

    int nblk = (NN + 127) / 128;
    for (int step = 0; step < 4; step++) {
        int do_proj = (step < 3) ? 1 : 0;
        k_pass<<<(2 * NN + 7) / 8, 256>>>();
        k_gru<<<nblk, 128, gru_smem>>>(bhh, x);
        dim3 pgrid(nblk, do_proj ? 2 : 1);
        k_post<<<pgrid, 128>>>(toW1, frW1, lpW1, lpb1, dec1, decb1, dec2, decb2, y,
                               (step == 3) ? out : nullptr, do_proj, step);
    }
    k_final<<<1, 32>>>(out);
}

// round 11
// speedup vs baseline: 1.1358x; 1.1358x over previous
#include <cuda_runtime.h>
#include <cuda_fp16.h>
#include <math.h>

#define NN 100000
#define EE 3200000
#define NB 98   // ceil(NN/1024)

typedef unsigned long long u64;

__device__ __forceinline__ u64 pk(float a, float b) {
    u64 r; asm("mov.b64 %0,{%1,%2};" : "=l"(r) : "f"(a), "f"(b)); return r;
}
__device__ __forceinline__ void upk(u64 v, float& a, float& b) {
    asm("mov.b64 {%0,%1},%2;" : "=f"(a), "=f"(b) : "l"(v));
}
__device__ __forceinline__ void ffma2(u64& d, u64 a, u64 b) {
    asm("fma.rn.f32x2 %0,%1,%2,%0;" : "+l"(d) : "l"(a), "l"(b));
}

// ---------------- device scratch ----------------
// unified GRU input stream, u64-paired, [row][n]:
//   rows 0-15: H   16-31: mean_to   32-47: mean_fr   48-63: lp-ReLU   64-65: x
__device__ __align__(16) u64 g_S[66 * NN];
__device__ __align__(16) __half g_PdtH[NN * 32];
__device__ __align__(16) __half g_PdfH[NN * 32];
__device__ __align__(16) __half g_PstH[NN * 32];
__device__ __align__(16) __half g_PsfH[NN * 32];
__device__ int   g_cnt_to[NN];
__device__ int   g_cnt_fr[NN];
__device__ float g_selfsum[NN];
__device__ float g_loss[4];

// CSR
__device__ int g_rowp_to[NN + 1];
__device__ int g_rowp_fr[NN + 1];
__device__ int g_cur_to[NN];
__device__ int g_cur_fr[NN];
__device__ __align__(16) u64 g_pay_to[EE];
__device__ __align__(16) u64 g_pay_fr[EE];
__device__ int g_blks[2 * NB];

// packed/folded weights
__device__ __align__(16) float g_G[96 * 132];
__device__ __align__(16) u64   g_Gp[132 * 48];   // [j][qp] = (G[2qp][j], G[2qp+1][j])
__device__ float g_bias[96];
__device__ float g_cto[96];
__device__ float g_cfr[96];
__device__ __align__(16) u64 g_ewp[96];          // [dir][row(wa0,wa1,b)][k] float-pairs

// ---------------- init ----------------
__global__ void k_init() {
    int t = blockIdx.x * blockDim.x + threadIdx.x;
    int nt = gridDim.x * blockDim.x;
    __half hz = __float2half(0.f);
    for (int i = t; i < 16 * NN; i += nt) g_S[i] = 0ull;   // H rows
    for (int i = t; i < 32 * NN; i += nt) {
        g_PdtH[i] = hz; g_PdfH[i] = hz; g_PstH[i] = hz; g_PsfH[i] = hz;
    }
    for (int i = t; i < NN; i += nt) {
        g_cnt_to[i] = 0; g_cnt_fr[i] = 0; g_selfsum[i] = 0.f;
    }
    if (t < 4) g_loss[t] = 0.f;
}

__global__ void k_count(const int* __restrict__ ei, const float* __restrict__ ea) {
    int e = blockIdx.x * blockDim.x + threadIdx.x;
    if (e >= EE) return;
    int s = ei[e];
    int d = ei[EE + e];
    if (s != d) {
        atomicAdd(&g_cnt_to[d], 1);
        atomicAdd(&g_cnt_fr[s], 1);
    } else {
        atomicAdd(&g_selfsum[s], ea[2 * e]);
    }
}

// ---------------- CSR build ----------------
__global__ void k_scanA() {
    __shared__ int sh[1024];
    int arr = blockIdx.y;
    int i = blockIdx.x * 1024 + threadIdx.x;
    const int* cnt = arr ? g_cnt_fr : g_cnt_to;
    int* rowp = arr ? g_rowp_fr : g_rowp_to;
    int v = (i < NN) ? cnt[i] : 0;
    sh[threadIdx.x] = v;
    __syncthreads();
#pragma unroll
    for (int off = 1; off < 1024; off <<= 1) {
        int t2 = (threadIdx.x >= off) ? sh[threadIdx.x - off] : 0;
        __syncthreads();
        sh[threadIdx.x] += t2;
        __syncthreads();
    }
    if (i < NN) rowp[i] = sh[threadIdx.x] - v;
    if (threadIdx.x == 1023) g_blks[arr * NB + blockIdx.x] = sh[1023];
}

__global__ void k_scanB() {
    int t = threadIdx.x;
    if (t < 2) {
        int acc = 0;
        for (int b = 0; b < NB; b++) {
            int v = g_blks[t * NB + b];
            g_blks[t * NB + b] = acc;
            acc += v;
        }
        (t ? g_rowp_fr : g_rowp_to)[NN] = acc;
    }
}

__global__ void k_scanC() {
    int arr = blockIdx.y;
    int i = blockIdx.x * 1024 + threadIdx.x;
    if (i >= NN) return;
    int* rowp = arr ? g_rowp_fr : g_rowp_to;
    int* cur  = arr ? g_cur_fr  : g_cur_to;
    int v = rowp[i] + g_blks[arr * NB + blockIdx.x];
    rowp[i] = v;
    cur[i] = v;
}

__global__ void k_scatter(const int* __restrict__ ei, const float* __restrict__ ea) {
    int e = blockIdx.x * blockDim.x + threadIdx.x;
    if (e >= EE) return;
    int s = ei[e];
    int d = ei[EE + e];
    if (s == d) return;
    __half2 eh = __floats2half2_rn(ea[2 * e], ea[2 * e + 1]);
    unsigned ehu = *(unsigned*)&eh;
    u64 hi = ((u64)ehu) << 32;
    int p1 = atomicAdd(&g_cur_to[d], 1);
    g_pay_to[p1] = hi | (unsigned)s;
    int p2 = atomicAdd(&g_cur_fr[s], 1);
    g_pay_fr[p2] = hi | (unsigned)d;
}

// ---------------- weight folding ----------------
__global__ void k_pack(const float* __restrict__ Wih, const float* __restrict__ bih,
                       const float* __restrict__ bhh,
                       const float* __restrict__ toW2, const float* __restrict__ tob2,
                       const float* __restrict__ frW2, const float* __restrict__ frb2,
                       const float* __restrict__ lpW2, const float* __restrict__ lpb2,
                       const float* __restrict__ toW1, const float* __restrict__ tob1,
                       const float* __restrict__ frW1, const float* __restrict__ frb1) {
    int t = blockIdx.x * blockDim.x + threadIdx.x;
    int nt = gridDim.x * blockDim.x;
    for (int idx = t; idx < 96 * 132; idx += nt) {
        int q = idx / 132, c = idx - q * 132;
        float v = 0.f;
        if (c < 32) {
            v = Wih[q * 131 + c];
        } else if (c < 64) {
            int j = c - 32;
            for (int i = 0; i < 32; i++) v += Wih[q * 131 + 32 + i] * toW2[i * 32 + j];
        } else if (c < 96) {
            int j = c - 64;
            for (int i = 0; i < 32; i++) v += Wih[q * 131 + 64 + i] * frW2[i * 32 + j];
        } else if (c < 128) {
            int j = c - 96;
            for (int i = 0; i < 32; i++) v += Wih[q * 131 + 96 + i] * lpW2[i * 32 + j];
        } else if (c < 131) {
            v = Wih[q * 131 + 128 + (c - 128)];
        }
        g_G[idx] = v;
    }
    for (int q = t; q < 96; q += nt) {
        float b = bih[q], ct = 0.f, cf = 0.f;
        for (int i = 0; i < 32; i++) {
            b  += Wih[q * 131 + 96 + i] * lpb2[i];
            ct += Wih[q * 131 + 32 + i] * tob2[i];
            cf += Wih[q * 131 + 64 + i] * frb2[i];
        }
        if (q < 64) b += bhh[q];
        g_bias[q] = b; g_cto[q] = ct; g_cfr[q] = cf;
    }
    // g_ewp[dir*48 + row*16 + k] = (w[2k], w[2k+1]) ; rows: wa0, wa1, bias
    for (int i = t; i < 96; i += nt) {
        int dir = i / 48, r = (i % 48) / 16, k = i & 15;
        const float* W1 = dir ? frW1 : toW1;
        const float* b1 = dir ? frb1 : tob1;
        float v0, v1;
        if (r < 2) { v0 = W1[(2 * k) * 66 + 64 + r]; v1 = W1[(2 * k + 1) * 66 + 64 + r]; }
        else       { v0 = b1[2 * k];                 v1 = b1[2 * k + 1]; }
        g_ewp[i] = pk(v0, v1);
    }
}

__global__ void k_pack2() {
    int t = blockIdx.x * blockDim.x + threadIdx.x;
    int nt = gridDim.x * blockDim.x;
    for (int idx = t; idx < 132 * 48; idx += nt) {
        int j = idx / 48, qp = idx - j * 48;
        g_Gp[idx] = pk(g_G[(2 * qp) * 132 + j], g_G[(2 * qp + 1) * 132 + j]);
    }
}

// ---------------- k_lp0: vt1 rows for H = 0, plus packed x rows ----------------
__global__ void k_lp0(const float* __restrict__ lpW1, const float* __restrict__ lpb1,
                      const float* __restrict__ x) {
    int n = blockIdx.x * blockDim.x + threadIdx.x;
    if (n >= NN) return;
    float lc = -g_selfsum[n];
#pragma unroll
    for (int k = 0; k < 16; k++) {
        float v0 = fmaxf(__ldg(&lpb1[2 * k])     + __ldg(&lpW1[(2 * k) * 65 + 64]) * lc, 0.f);
        float v1 = fmaxf(__ldg(&lpb1[2 * k + 1]) + __ldg(&lpW1[(2 * k + 1) * 65 + 64]) * lc, 0.f);
        g_S[(48 + k) * NN + n] = pk(v0, v1);
    }
    float x0 = __ldg(&x[n * 3]), x1 = __ldg(&x[n * 3 + 1]), x2 = __ldg(&x[n * 3 + 2]);
    g_S[64 * NN + n] = pk(x0, x1);
    g_S[65 * NN + n] = pk(x2, 0.f);
}

// ---------------- edge pass: 16-lane group per node, transposed mean output ----------------
__global__ __launch_bounds__(256) void k_pass() {
    int gid = (blockIdx.x * 256 + threadIdx.x) >> 4;
    int k = threadIdx.x & 15;
    int dir = gid >= NN;
    int n = gid - dir * NN;
    if (n >= NN) return;

    const int*    rowp = dir ? g_rowp_fr : g_rowp_to;
    const u64*    pay  = dir ? g_pay_fr  : g_pay_to;
    const __half* stat = dir ? g_PsfH    : g_PdtH;
    const __half* gat  = dir ? g_PdfH    : g_PstH;
    u64*          outp = &g_S[(16 + dir * 16 + k) * NN];

    float wa00, wa01, wa10, wa11, b0, b1;
    upk(__ldg(&g_ewp[dir * 48 + k]),      wa00, wa01);
    upk(__ldg(&g_ewp[dir * 48 + 16 + k]), wa10, wa11);
    upk(__ldg(&g_ewp[dir * 48 + 32 + k]), b0, b1);

    int beg = __ldg(&rowp[n]);
    int end = __ldg(&rowp[n + 1]);
    float2 sf = __half22float2(*(const __half2*)&stat[n * 32 + 2 * k]);
    float base0 = sf.x + b0, base1 = sf.y + b1;
    float acc0 = 0.f, acc1 = 0.f;

    int e = beg;
    if ((e & 1) && e < end) {
        u64 p = __ldg(&pay[e]);
        int idx = (int)(unsigned)p;
        unsigned ehu = (unsigned)(p >> 32);
        float2 eaf = __half22float2(*(__half2*)&ehu);
        float2 g = __half22float2(*(const __half2*)&gat[idx * 32 + 2 * k]);
        acc0 += fmaxf(base0 + g.x + eaf.x * wa00 + eaf.y * wa10, 0.f);
        acc1 += fmaxf(base1 + g.y + eaf.x * wa01 + eaf.y * wa11, 0.f);
        e++;
    }
    for (; e + 1 < end; e += 2) {
        uint4 p2 = __ldg((const uint4*)&pay[e]);
        float2 ea0 = __half22float2(*(__half2*)&p2.y);
        float2 ea1 = __half22float2(*(__half2*)&p2.w);
        float2 g0 = __half22float2(*(const __half2*)&gat[(int)p2.x * 32 + 2 * k]);
        float2 g1 = __half22float2(*(const __half2*)&gat[(int)p2.z * 32 + 2 * k]);
        acc0 += fmaxf(base0 + g0.x + ea0.x * wa00 + ea0.y * wa10, 0.f);
        acc1 += fmaxf(base1 + g0.y + ea0.x * wa01 + ea0.y * wa11, 0.f);
        acc0 += fmaxf(base0 + g1.x + ea1.x * wa00 + ea1.y * wa10, 0.f);
        acc1 += fmaxf(base1 + g1.y + ea1.x * wa01 + ea1.y * wa11, 0.f);
    }
    if (e < end) {
        u64 p = __ldg(&pay[e]);
        int idx = (int)(unsigned)p;
        unsigned ehu = (unsigned)(p >> 32);
        float2 eaf = __half22float2(*(__half2*)&ehu);
        float2 g = __half22float2(*(const __half2*)&gat[idx * 32 + 2 * k]);
        acc0 += fmaxf(base0 + g.x + eaf.x * wa00 + eaf.y * wa10, 0.f);
        acc1 += fmaxf(base1 + g.y + eaf.x * wa01 + eaf.y * wa11, 0.f);
    }
    int cnt = end - beg;
    float rt = cnt > 0 ? 1.f / (float)cnt : 0.f;
    outp[n] = pk(acc0 * rt, acc1 * rt);   // mean, pre-scaled
}

// ---------------- k_gru: output-stationary GEMV, coalesced row stream ----------------
__device__ __forceinline__ void consume(u64* acc, const u64* sGp, int j2, u64 c) {
    float v0, v1; upk(c, v0, v1);
    u64 s0 = pk(v0, v0), s1 = pk(v1, v1);
    const u64* w0p = &sGp[(2 * j2) * 48];
    const u64* w1p = w0p + 48;
#pragma unroll
    for (int qb = 0; qb < 24; qb++) {
        ulonglong2 w = *(const ulonglong2*)&w0p[qb * 2];
        ffma2(acc[qb * 2], w.x, s0);
        ffma2(acc[qb * 2 + 1], w.y, s0);
    }
#pragma unroll
    for (int qb = 0; qb < 24; qb++) {
        ulonglong2 w = *(const ulonglong2*)&w1p[qb * 2];
        ffma2(acc[qb * 2], w.x, s1);
        ffma2(acc[qb * 2 + 1], w.y, s1);
    }
}

__global__ __launch_bounds__(128, 3) void k_gru(const float* __restrict__ bhh) {
    extern __shared__ u64 smu[];
    u64*   sGp  = smu;                       // 6336 u64
    float* sb   = (float*)(smu + 6336);      // 96
    float* sct  = sb + 96;                   // 96
    float* scf  = sct + 96;                  // 96
    float* sbhn = scf + 96;                  // 32

    for (int i = threadIdx.x; i < 6336; i += 128) sGp[i] = g_Gp[i];
    for (int i = threadIdx.x; i < 96; i += 128) {
        sb[i] = g_bias[i]; sct[i] = g_cto[i]; scf[i] = g_cfr[i];
    }
    if (threadIdx.x < 32) sbhn[threadIdx.x] = bhh[64 + threadIdx.x];
    __syncthreads();

    int n = blockIdx.x * 128 + threadIdx.x;
    if (n >= NN) return;

    float ft = (__ldg(&g_cnt_to[n]) > 0) ? 1.f : 0.f;
    float ff = (__ldg(&g_cnt_fr[n]) > 0) ? 1.f : 0.f;

    u64 acc[48];
#pragma unroll
    for (int qp = 0; qp < 48; qp++) {
        int q0 = 2 * qp, q1 = q0 + 1;
        acc[qp] = pk(sb[q0] + ft * sct[q0] + ff * scf[q0],
                     sb[q1] + ft * sct[q1] + ff * scf[q1]);
    }

    // stream 66 coalesced u64 rows, prefetch depth 2
    u64 c0 = __ldg(&g_S[n]);
    u64 c1 = __ldg(&g_S[NN + n]);
    for (int j2 = 0; j2 < 66; j2++) {
        u64 cur = c0;
        c0 = c1;
        c1 = (j2 + 2 < 66) ? __ldg(&g_S[(j2 + 2) * NN + n]) : 0ull;
        consume(acc, sGp, j2, cur);
    }

#pragma unroll
    for (int i = 0; i < 16; i++) {
        float aR0, aR1, aZ0, aZ1, aN0, aN1;
        upk(acc[i], aR0, aR1);
        upk(acc[16 + i], aZ0, aZ1);
        upk(acc[32 + i], aN0, aN1);
        int q0 = 2 * i, q1 = q0 + 1;
        float r0 = 1.f / (1.f + __expf(-aR0));
        float r1 = 1.f / (1.f + __expf(-aR1));
        float z0 = 1.f / (1.f + __expf(-aZ0));
        float z1 = 1.f / (1.f + __expf(-aZ1));
        float tn0 = aN0 + r0 * sbhn[q0];
        float tn1 = aN1 + r1 * sbhn[q1];
        float th0 = 2.f / (1.f + __expf(-2.f * tn0)) - 1.f;
        float th1 = 2.f / (1.f + __expf(-2.f * tn1)) - 1.f;
        float h0, h1; upk(g_S[i * NN + n], h0, h1);
        h0 += 0.5f * (1.f - z0) * th0;   // ALPHA = 0.5
        h1 += 0.5f * (1.f - z1) * th1;
        g_S[i * NN + n] = pk(h0, h1);
    }
}

// ---------------- k_post: 4 parallel slices ----------------
// y=0: decode+loss   y=1: proj m0/m1 (Pdt,Pdf)   y=2: proj m2/m3 (Pst,Psf)   y=3: lp->vt1
__global__ __launch_bounds__(128) void k_post(
        const float* __restrict__ toW1, const float* __restrict__ frW1,
        const float* __restrict__ lpW1, const float* __restrict__ lpb1,
        const float* __restrict__ dec1, const float* __restrict__ decb1,
        const float* __restrict__ dec2, const float* __restrict__ decb2,
        const float* __restrict__ y, float* __restrict__ outF, int loss_idx) {
    __shared__ float sW[2048];
    __shared__ float sD2[64];
    __shared__ float sDb1[32];
    __shared__ float sDb2[2];

    int slice = blockIdx.y;
    if (slice == 0) {
        for (int i = threadIdx.x; i < 1024; i += 128) sW[i] = dec1[i];
        if (threadIdx.x < 64) sD2[threadIdx.x] = dec2[threadIdx.x];
        if (threadIdx.x < 32) sDb1[threadIdx.x] = decb1[threadIdx.x];
        if (threadIdx.x < 2)  sDb2[threadIdx.x] = decb2[threadIdx.x];
    } else if (slice <= 2) {
        int half = slice - 1;
        for (int i = threadIdx.x; i < 2048; i += 128) {
            int m = half * 2 + (i >> 10), r = i & 1023, ii = r >> 5, j = r & 31;
            float v;
            if (m == 0)      v = toW1[ii * 66 + j];        // Pdt
            else if (m == 1) v = frW1[ii * 66 + 32 + j];   // Pdf
            else if (m == 2) v = toW1[ii * 66 + 32 + j];   // Pst
            else             v = frW1[ii * 66 + j];        // Psf
            sW[i] = v;
        }
    } else {
        for (int i = threadIdx.x; i < 1152; i += 128) {
            int tq = i / 36, c = i - tq * 36;
            float v = 0.f;
            if (c < 32)       v = lpW1[tq * 65 + c] + lpW1[tq * 65 + 32 + c];
            else if (c == 32) v = lpW1[tq * 65 + 64];
            sW[i] = v;
        }
        if (threadIdx.x < 32) sDb1[threadIdx.x] = lpb1[threadIdx.x];
    }
    __syncthreads();

    int n = blockIdx.x * 128 + threadIdx.x;
    if (n >= NN) return;

    u64 vHp[16];
#pragma unroll
    for (int k = 0; k < 16; k++) vHp[k] = __ldg(&g_S[k * NN + n]);

    if (slice == 0) {
        float F0 = sDb2[0], F1 = sDb2[1];
        for (int i = 0; i < 32; i++) {
            u64 acc = pk(sDb1[i], 0.f);
#pragma unroll
            for (int j4 = 0; j4 < 8; j4++) {
                ulonglong2 w = *(const ulonglong2*)&sW[i * 32 + j4 * 4];
                ffma2(acc, w.x, vHp[j4 * 2]);
                ffma2(acc, w.y, vHp[j4 * 2 + 1]);
            }
            float lo, hi; upk(acc, lo, hi);
            float a = fmaxf(lo + hi, 0.f);
            F0 += sD2[i] * a;
            F1 += sD2[32 + i] * a;
        }
        float d0 = F0 - y[n * 2], d1 = F1 - y[n * 2 + 1];
        float sse = d0 * d0 + d1 * d1;
        if (outF) { outF[n * 2] = F0; outF[n * 2 + 1] = F1; }
#pragma unroll
        for (int o = 16; o; o >>= 1) sse += __shfl_down_sync(0xffffffffu, sse, o);
        if ((threadIdx.x & 31) == 0) atomicAdd(&g_loss[loss_idx], sse);
    } else if (slice <= 2) {
        int half = slice - 1;
        __half* outA = half ? g_PstH : g_PdtH;
        __half* outB = half ? g_PsfH : g_PdfH;
        for (int i4 = 0; i4 < 8; i4++) {
            u64 A[8];
#pragma unroll
            for (int t = 0; t < 8; t++) A[t] = 0ull;
#pragma unroll
            for (int j4 = 0; j4 < 8; j4++) {
                u64 vlo = vHp[j4 * 2], vhi = vHp[j4 * 2 + 1];
#pragma unroll
                for (int mm = 0; mm < 2; mm++) {
#pragma unroll
                    for (int ii = 0; ii < 4; ii++) {
                        ulonglong2 w = *(const ulonglong2*)&sW[mm * 1024 + (i4 * 4 + ii) * 32 + j4 * 4];
                        ffma2(A[mm * 4 + ii], w.x, vlo);
                        ffma2(A[mm * 4 + ii], w.y, vhi);
                    }
                }
            }
            __half2 hA01, hA23, hB01, hB23;
            float l0, h0, l1, h1, l2, h2, l3, h3;
            upk(A[0], l0, h0); upk(A[1], l1, h1); upk(A[2], l2, h2); upk(A[3], l3, h3);
            hA01 = __floats2half2_rn(l0 + h0, l1 + h1);
            hA23 = __floats2half2_rn(l2 + h2, l3 + h3);
            upk(A[4], l0, h0); upk(A[5], l1, h1); upk(A[6], l2, h2); upk(A[7], l3, h3);
            hB01 = __floats2half2_rn(l0 + h0, l1 + h1);
            hB23 = __floats2half2_rn(l2 + h2, l3 + h3);
            uint2 stA, stB;
            stA.x = *(unsigned*)&hA01; stA.y = *(unsigned*)&hA23;
            stB.x = *(unsigned*)&hB01; stB.y = *(unsigned*)&hB23;
            *(uint2*)&outA[n * 32 + i4 * 4] = stA;
            *(uint2*)&outB[n * 32 + i4 * 4] = stB;
        }
    } else {
        float lc = -g_selfsum[n];
#pragma unroll
        for (int i2 = 0; i2 < 16; i2++) {
            int i0 = 2 * i2;
            u64 acc0 = pk(sDb1[i0]     + sW[i0 * 36 + 32] * lc, 0.f);
            u64 acc1 = pk(sDb1[i0 + 1] + sW[(i0 + 1) * 36 + 32] * lc, 0.f);
#pragma unroll
            for (int j4 = 0; j4 < 8; j4++) {
                ulonglong2 w0 = *(const ulonglong2*)&sW[i0 * 36 + j4 * 4];
                ulonglong2 w1 = *(const ulonglong2*)&sW[(i0 + 1) * 36 + j4 * 4];
                ffma2(acc0, w0.x, vHp[j4 * 2]); ffma2(acc0, w0.y, vHp[j4 * 2 + 1]);
                ffma2(acc1, w1.x, vHp[j4 * 2]); ffma2(acc1, w1.y, vHp[j4 * 2 + 1]);
            }
            float a0, b0, a1, b1;
            upk(acc0, a0, b0); upk(acc1, a1, b1);
            g_S[(48 + i2) * NN + n] = pk(fmaxf(a0 + b0, 0.f), fmaxf(a1 + b1, 0.f));
        }
    }
}

// ---------------- finalize losses ----------------
__global__ void k_final(float* __restrict__ out) {
    if (blockIdx.x == 0 && threadIdx.x == 0) {
        float inv = 1.f / (2.f * (float)NN);
        float l0 = g_loss[0] * inv;
        float l1 = g_loss[1] * inv;
        float l2 = g_loss[2] * inv;
        float l3 = g_loss[3] * inv;
        out[200000] = 0.729f * l0 + 0.81f * l1 + 0.9f * l2 + l3;
        out[200001] = l0; out[200002] = l1; out[200003] = l2; out[200004] = l3;
    }
}

// ---------------- launch ----------------
extern "C" void kernel_launch(void* const* d_in, const int* in_sizes, int n_in,
                              void* d_out, int out_size) {
    const float* x    = (const float*)d_in[0];
    const float* y    = (const float*)d_in[1];
    const int*   ei   = (const int*)d_in[2];
    const float* ea   = (const float*)d_in[3];
    const float* toW1 = (const float*)d_in[4];
    const float* tob1 = (const float*)d_in[5];
    const float* toW2 = (const float*)d_in[6];
    const float* tob2 = (const float*)d_in[7];
    const float* frW1 = (const float*)d_in[8];
    const float* frb1 = (const float*)d_in[9];
    const float* frW2 = (const float*)d_in[10];
    const float* frb2 = (const float*)d_in[11];
    const float* lpW1 = (const float*)d_in[12];
    const float* lpb1 = (const float*)d_in[13];
    const float* lpW2 = (const float*)d_in[14];
    const float* lpb2 = (const float*)d_in[15];
    const float* Wih  = (const float*)d_in[16];
    const float* bih  = (const float*)d_in[17];
    // d_in[18] = gru_Whh (unused: h0 = 0)
    const float* bhh  = (const float*)d_in[19];
    const float* dec1 = (const float*)d_in[20];
    const float* decb1= (const float*)d_in[21];
    const float* dec2 = (const float*)d_in[22];
    const float* decb2= (const float*)d_in[23];
    float* out = (float*)d_out;

    const int gru_smem = 6336 * 8 + 320 * 4;   // 51968 bytes
    cudaFuncSetAttribute(k_gru, cudaFuncAttributeMaxDynamicSharedMemorySize, gru_smem);

    k_init<<<1024, 256>>>();
    k_count<<<(EE + 255) / 256, 256>>>(ei, ea);
    k_pack<<<8, 256>>>(Wih, bih, bhh, toW2, tob2, frW2, frb2, lpW2, lpb2,
                       toW1, tob1, frW1, frb1);
    k_pack2<<<8, 256>>>();
    dim3 sgrid(NB, 2);
    k_scanA<<<sgrid, 1024>>>();
    k_scanB<<<1, 32>>>();
    k_scanC<<<sgrid, 1024>>>();
    k_scatter<<<(EE + 255) / 256, 256>>>(ei, ea);
    k_lp0<<<(NN + 255) / 256, 256>>>(lpW1, lpb1, x);

    int nblk = (NN + 127) / 128;
    for (int step = 0; step < 4; step++) {
        int do_proj = (step < 3) ? 1 : 0;
        k_pass<<<12500, 256>>>();
        k_gru<<<nblk, 128, gru_smem>>>(bhh);
        dim3 pgrid(nblk, do_proj ? 4 : 1);
        k_post<<<pgrid, 128>>>(toW1, frW1, lpW1, lpb1, dec1, decb1, dec2, decb2, y,
                               (step == 3) ? out : nullptr, step);
    }
    k_final<<<1, 32>>>(out);
}